// round 7
// baseline (speedup 1.0000x reference)
#include <cuda_runtime.h>
#include <cuda_bf16.h>
#include <math.h>
#include <stdint.h>

#define B_ 2
#define T_ 2048
#define D_ 1024
#define H_ 16
#define DH_ 64
#define SCALE_ 0.03125f     /* 1/sqrt(1024) exactly */

// ============================================================================
// Scratch (static device globals — no allocation in kernel_launch)
// ============================================================================
__device__ float g_CTX[(size_t)B_*T_*D_];
__device__ __nv_bfloat16 g_Ah[(size_t)4096*1024];
__device__ __nv_bfloat16 g_Al[(size_t)4096*1024];
__device__ __nv_bfloat16 g_Wh[(size_t)1024*1024];
__device__ __nv_bfloat16 g_Wl[(size_t)1024*1024];
__device__ __nv_bfloat16 g_Qh[(size_t)B_*H_*T_*DH_];
__device__ __nv_bfloat16 g_Ql[(size_t)B_*H_*T_*DH_];
__device__ __nv_bfloat16 g_Kh[(size_t)B_*H_*T_*DH_];   // compacted
__device__ __nv_bfloat16 g_Kl[(size_t)B_*H_*T_*DH_];   // compacted
__device__ __nv_bfloat16 g_Vh[(size_t)B_*H_*T_*DH_];   // compacted
__device__ __nv_bfloat16 g_Vl[(size_t)B_*H_*T_*DH_];   // compacted
__device__ int g_pos[B_*T_];
__device__ int g_cnt[B_];

// ============================================================================
// mma.sync / ldmatrix / cp.async helpers (base-target PTX)
// ============================================================================
__device__ __forceinline__ unsigned smem_u32(const void* p) {
    unsigned a;
    asm("{ .reg .u64 t; cvta.to.shared.u64 t, %1; cvt.u32.u64 %0, t; }"
        : "=r"(a) : "l"(p));
    return a;
}
__device__ __forceinline__ void mma_bf(float* c, const unsigned* a, const unsigned* b) {
    asm volatile(
        "mma.sync.aligned.m16n8k16.row.col.f32.bf16.bf16.f32 "
        "{%0,%1,%2,%3}, {%4,%5,%6,%7}, {%8,%9}, {%0,%1,%2,%3};"
        : "+f"(c[0]), "+f"(c[1]), "+f"(c[2]), "+f"(c[3])
        : "r"(a[0]), "r"(a[1]), "r"(a[2]), "r"(a[3]), "r"(b[0]), "r"(b[1]));
}
__device__ __forceinline__ void ldsm4(unsigned* r, unsigned a) {
    asm volatile("ldmatrix.sync.aligned.m8n8.x4.shared.b16 {%0,%1,%2,%3}, [%4];"
        : "=r"(r[0]), "=r"(r[1]), "=r"(r[2]), "=r"(r[3]) : "r"(a));
}
__device__ __forceinline__ void ldsm4t(unsigned* r, unsigned a) {
    asm volatile("ldmatrix.sync.aligned.m8n8.x4.trans.shared.b16 {%0,%1,%2,%3}, [%4];"
        : "=r"(r[0]), "=r"(r[1]), "=r"(r[2]), "=r"(r[3]) : "r"(a));
}
#define CP16(dst_u32, src_ptr) \
    asm volatile("cp.async.cg.shared.global [%0], [%1], 16;" \
        :: "r"(dst_u32), "l"(src_ptr) : "memory")
#define CP_COMMIT() asm volatile("cp.async.commit_group;" ::: "memory")
#define CP_WAIT1()  asm volatile("cp.async.wait_group 1;"  ::: "memory")

// ============================================================================
// scan_mask: per-batch exclusive prefix scan of mask -> compact positions
// ============================================================================
__global__ void __launch_bounds__(1024) scan_mask(const int* __restrict__ mask)
{
    __shared__ int ps[1024];
    const int b = blockIdx.x, i = threadIdx.x;
    const int a0 = (mask[b*T_ + 2*i]     != 0);
    const int a1 = (mask[b*T_ + 2*i + 1] != 0);
    ps[i] = a0 + a1;
    __syncthreads();
    for (int off = 1; off < 1024; off <<= 1) {
        int v = ps[i] + ((i >= off) ? ps[i - off] : 0);
        __syncthreads();
        ps[i] = v;
        __syncthreads();
    }
    const int excl = (i > 0) ? ps[i-1] : 0;
    g_pos[b*T_ + 2*i]     = a0 ? excl : -1;
    g_pos[b*T_ + 2*i + 1] = a1 ? (excl + a0) : -1;
    if (i == 1023) g_cnt[b] = ps[1023];
}

// ============================================================================
// conv_split: fp32 -> (hi, lo) bf16, elementwise, vectorized
// ============================================================================
__global__ void __launch_bounds__(256) conv_split(
    const float* __restrict__ x, __nv_bfloat16* __restrict__ hi,
    __nv_bfloat16* __restrict__ lo, int n4)
{
    int i = blockIdx.x * 256 + threadIdx.x;
    if (i >= n4) return;
    float4 v = ((const float4*)x)[i];
    __nv_bfloat16 h0 = __float2bfloat16_rn(v.x);
    __nv_bfloat16 h1 = __float2bfloat16_rn(v.y);
    __nv_bfloat16 h2 = __float2bfloat16_rn(v.z);
    __nv_bfloat16 h3 = __float2bfloat16_rn(v.w);
    __nv_bfloat162 ha; ha.x = h0; ha.y = h1;
    __nv_bfloat162 hb; hb.x = h2; hb.y = h3;
    __nv_bfloat162 la, lb;
    la.x = __float2bfloat16_rn(v.x - __bfloat162float(h0));
    la.y = __float2bfloat16_rn(v.y - __bfloat162float(h1));
    lb.x = __float2bfloat16_rn(v.z - __bfloat162float(h2));
    lb.y = __float2bfloat16_rn(v.w - __bfloat162float(h3));
    ((__nv_bfloat162*)hi)[2*i]   = ha;
    ((__nv_bfloat162*)hi)[2*i+1] = hb;
    ((__nv_bfloat162*)lo)[2*i]   = la;
    ((__nv_bfloat162*)lo)[2*i+1] = lb;
}

// ============================================================================
// GEMM via mma.sync: Y(4096x1024) = A @ W + bias, split-bf16 3-stream.
// cp.async 2-stage pipelined mainloop (loads for kc+1 overlap mma of kc).
// Stage layout (bytes): Ah[128][40]=10240, Al=10240, Wh[32][136]=8704, Wl=8704
// mode 0: Q projection  -> bf16 hi+lo, scatter [B,H,T,64]
// mode 1: K/V projection-> bf16 hi+lo, scatter to COMPACTED rows (pos)
// mode 2: dense fp32 output (out projection)
// ============================================================================
#define GST 37888   /* stage stride in bytes */
#define G_AL_OFF 10240
#define G_WH_OFF 20480
#define G_WL_OFF 29184
#define GEMM_SMEM (2*GST)

__global__ void __launch_bounds__(256) gemm_mma(
    const __nv_bfloat16* __restrict__ Ah, const __nv_bfloat16* __restrict__ Al,
    const __nv_bfloat16* __restrict__ Wh, const __nv_bfloat16* __restrict__ Wl,
    const float* __restrict__ bias,
    float* __restrict__ Yf,
    __nv_bfloat16* __restrict__ Yh, __nv_bfloat16* __restrict__ Yl,
    int mode)
{
    extern __shared__ __align__(16) char gsm[];

    const int tid = threadIdx.x, lane = tid & 31, wid = tid >> 5;
    const int wm = wid >> 2, wn = wid & 3;
    const int m0 = blockIdx.y << 7, n0 = blockIdx.x << 7;

    float c[4][4][4];
    #pragma unroll
    for (int i = 0; i < 4; i++)
        #pragma unroll
        for (int j = 0; j < 4; j++)
            #pragma unroll
            for (int e = 0; e < 4; e++) c[i][j][e] = 0.f;

    const int l15 = lane & 15, lh8 = (lane >> 4) << 3;
    const unsigned smb = smem_u32(gsm);

    // cp.async chunk maps (2 chunks/thread per 8KB matrix)
    // A: 128 rows x 32 cols bf16 (64B/row = 4 chunks); W: 32 rows x 128 cols (16 chunks)
    int a_row[2], a_c8[2], w_row[2], w_c8[2];
    #pragma unroll
    for (int t = 0; t < 2; t++) {
        int ch = tid + t*256;
        a_row[t] = ch >> 2;  a_c8[t] = (ch & 3) << 3;
        w_row[t] = ch >> 4;  w_c8[t] = (ch & 15) << 3;
    }

    // Issue one k-chunk's loads into stage s
    auto issue = [&](int s, int k0) {
        const unsigned base = smb + s*GST;
        #pragma unroll
        for (int t = 0; t < 2; t++) {
            unsigned aso = base + (unsigned)(a_row[t]*80 + a_c8[t]*2);
            size_t ago = (size_t)(m0 + a_row[t])*1024 + k0 + a_c8[t];
            CP16(aso,            Ah + ago);
            CP16(aso + G_AL_OFF, Al + ago);
            unsigned wso = base + G_WH_OFF + (unsigned)(w_row[t]*272 + w_c8[t]*2);
            size_t wgo = (size_t)(k0 + w_row[t])*1024 + n0 + w_c8[t];
            CP16(wso,                       Wh + wgo);
            CP16(wso + (G_WL_OFF-G_WH_OFF), Wl + wgo);
        }
    };

    issue(0, 0);
    CP_COMMIT();

    for (int kc = 0; kc < 32; kc++) {
        const int buf = kc & 1;
        if (kc + 1 < 32) issue(buf ^ 1, (kc+1) << 5);
        CP_COMMIT();
        CP_WAIT1();
        __syncthreads();

        const __nv_bfloat16* sAh = (const __nv_bfloat16*)(gsm + buf*GST);
        const __nv_bfloat16* sAl = (const __nv_bfloat16*)(gsm + buf*GST + G_AL_OFF);
        const __nv_bfloat16* sWh = (const __nv_bfloat16*)(gsm + buf*GST + G_WH_OFF);
        const __nv_bfloat16* sWl = (const __nv_bfloat16*)(gsm + buf*GST + G_WL_OFF);

        #pragma unroll
        for (int kk = 0; kk < 32; kk += 16) {
            unsigned a[4][4], bh_[4][2], bl_[4][2], t4[4];
            #pragma unroll
            for (int mi = 0; mi < 4; mi++)
                ldsm4(a[mi], smem_u32(&sAh[(wm*64 + mi*16 + l15)*40 + kk + lh8]));
            #pragma unroll
            for (int p = 0; p < 2; p++) {
                ldsm4t(t4, smem_u32(&sWh[(kk + l15)*136 + wn*32 + p*16 + lh8]));
                bh_[2*p][0]=t4[0]; bh_[2*p][1]=t4[1];
                bh_[2*p+1][0]=t4[2]; bh_[2*p+1][1]=t4[3];
                ldsm4t(t4, smem_u32(&sWl[(kk + l15)*136 + wn*32 + p*16 + lh8]));
                bl_[2*p][0]=t4[0]; bl_[2*p][1]=t4[1];
                bl_[2*p+1][0]=t4[2]; bl_[2*p+1][1]=t4[3];
            }
            #pragma unroll
            for (int mi = 0; mi < 4; mi++)
                #pragma unroll
                for (int ni = 0; ni < 4; ni++) mma_bf(c[mi][ni], a[mi], bh_[ni]);
            #pragma unroll
            for (int mi = 0; mi < 4; mi++)
                #pragma unroll
                for (int ni = 0; ni < 4; ni++) mma_bf(c[mi][ni], a[mi], bl_[ni]);
            #pragma unroll
            for (int mi = 0; mi < 4; mi++)
                ldsm4(a[mi], smem_u32(&sAl[(wm*64 + mi*16 + l15)*40 + kk + lh8]));
            #pragma unroll
            for (int mi = 0; mi < 4; mi++)
                #pragma unroll
                for (int ni = 0; ni < 4; ni++) mma_bf(c[mi][ni], a[mi], bh_[ni]);
        }
        __syncthreads();
    }

    // Epilogue
    const int rA = lane >> 2, c2 = (lane & 3) << 1;
    #pragma unroll
    for (int mi = 0; mi < 4; mi++) {
        const int rowA = m0 + wm*64 + mi*16 + rA;
        const int rowB = rowA + 8;
        int pA = rowA & (T_-1), pB = rowB & (T_-1);
        if (mode == 1) { pA = g_pos[rowA]; pB = g_pos[rowB]; }
        #pragma unroll
        for (int ni = 0; ni < 4; ni++) {
            const int col = n0 + wn*32 + ni*8 + c2;
            float2 bb = *(const float2*)(bias + col);
            float v00 = c[mi][ni][0] + bb.x, v01 = c[mi][ni][1] + bb.y;
            float v10 = c[mi][ni][2] + bb.x, v11 = c[mi][ni][3] + bb.y;
            if (mode == 2) {
                float2 w0; w0.x = v00; w0.y = v01;
                float2 w1; w1.x = v10; w1.y = v11;
                *(float2*)(Yf + (size_t)rowA * 1024 + col) = w0;
                *(float2*)(Yf + (size_t)rowB * 1024 + col) = w1;
            } else {
                const int hh = col >> 6, dd = col & 63;
                const int bA = rowA >> 11, bB = rowB >> 11;
                __nv_bfloat16 h00 = __float2bfloat16_rn(v00);
                __nv_bfloat16 h01 = __float2bfloat16_rn(v01);
                __nv_bfloat16 h10 = __float2bfloat16_rn(v10);
                __nv_bfloat16 h11 = __float2bfloat16_rn(v11);
                __nv_bfloat162 ph0; ph0.x=h00; ph0.y=h01;
                __nv_bfloat162 ph1; ph1.x=h10; ph1.y=h11;
                __nv_bfloat162 pl0, pl1;
                pl0.x = __float2bfloat16_rn(v00 - __bfloat162float(h00));
                pl0.y = __float2bfloat16_rn(v01 - __bfloat162float(h01));
                pl1.x = __float2bfloat16_rn(v10 - __bfloat162float(h10));
                pl1.y = __float2bfloat16_rn(v11 - __bfloat162float(h11));
                if (pA >= 0) {
                    size_t oA = (((size_t)(bA*H_ + hh))*T_ + pA)*64 + dd;
                    *(__nv_bfloat162*)(Yh + oA) = ph0;
                    *(__nv_bfloat162*)(Yl + oA) = pl0;
                }
                if (pB >= 0) {
                    size_t oB = (((size_t)(bB*H_ + hh))*T_ + pB)*64 + dd;
                    *(__nv_bfloat162*)(Yh + oB) = ph1;
                    *(__nv_bfloat162*)(Yl + oB) = pl1;
                }
            }
        }
    }
}

// ============================================================================
// Flash attention, compacted keys, 64-key tiles, 3-stream numerics
// (unchanged from R5 passing version)
// ============================================================================
#define ATT_QH   0
#define ATT_QL   18432
#define ATT_K    36864
#define ATT_V    73728
#define ATT_PH   110592
#define ATT_PL   129024
#define ATT_PSUM 147456
#define ATT_LS   149504
#define ATT_SMEM 150016

__global__ void __launch_bounds__(256) attn_mma()
{
    extern __shared__ __align__(16) char sm[];
    __nv_bfloat16* sQh = (__nv_bfloat16*)(sm + ATT_QH);
    __nv_bfloat16* sQl = (__nv_bfloat16*)(sm + ATT_QL);
    __nv_bfloat16* sPh = (__nv_bfloat16*)(sm + ATT_PH);
    __nv_bfloat16* sPl = (__nv_bfloat16*)(sm + ATT_PL);
    float* psum = (float*)(sm + ATT_PSUM);
    float* l_s  = (float*)(sm + ATT_LS);

    const int tid = threadIdx.x, lane = tid & 31, wid = tid >> 5;
    const int wm = wid >> 2, wn = wid & 3;
    const int qt0 = blockIdx.x << 7;
    const int hh = blockIdx.y, bb = blockIdx.z;
    const size_t base = ((size_t)(bb*H_ + hh)) * T_ * DH_;
    const int nv = g_cnt[bb];
    const int nt = (nv + 63) >> 6;

    const int r = tid >> 1, cofs = (tid & 1) << 5;
    const int l15 = lane & 15, lh8 = (lane >> 4) << 3;
    const int bn  = (lane & 7) + ((lane >> 4) << 3), bk8 = ((lane >> 3) & 1) << 3;
    const int rA0 = lane >> 2, c2 = (lane & 3) << 1;

    const unsigned smK = smem_u32(sm + ATT_K);
    const unsigned smV = smem_u32(sm + ATT_V);

    int ld_row[2], ld_c8[2];
    #pragma unroll
    for (int t = 0; t < 2; t++) {
        int ch = tid + t*256;
        ld_row[t] = ch >> 3;
        ld_c8[t]  = (ch & 7) << 3;
    }

    {
        const uint4* s1 = (const uint4*)(g_Qh + base + (size_t)(qt0 + r)*64 + cofs);
        uint4* d1 = (uint4*)(sQh + r*72 + cofs);
        d1[0]=s1[0]; d1[1]=s1[1]; d1[2]=s1[2]; d1[3]=s1[3];
        const uint4* s2 = (const uint4*)(g_Ql + base + (size_t)(qt0 + r)*64 + cofs);
        uint4* d2 = (uint4*)(sQl + r*72 + cofs);
        d2[0]=s2[0]; d2[1]=s2[1]; d2[2]=s2[2]; d2[3]=s2[3];
    }
    if (tid < 128) l_s[tid] = 0.f;

    float o[4][2][4];
    #pragma unroll
    for (int i = 0; i < 4; i++)
        #pragma unroll
        for (int j = 0; j < 2; j++)
            #pragma unroll
            for (int e = 0; e < 4; e++) o[i][j][e] = 0.f;

    #pragma unroll
    for (int t = 0; t < 2; t++) {
        unsigned so = (unsigned)((ld_row[t]*72 + ld_c8[t]) * 2);
        size_t go = base + (size_t)ld_row[t]*64 + ld_c8[t];
        CP16(smK + so,         g_Kh + go);
        CP16(smK + 9216u + so, g_Kl + go);
        CP16(smV + so,         g_Vh + go);
        CP16(smV + 9216u + so, g_Vl + go);
    }
    CP_COMMIT();

    for (int kt = 0; kt < nt; kt++) {
        const int buf = kt & 1;
        if (kt + 1 < nt) {
            const size_t gofs = base + ((size_t)(kt+1) << 6) * 64;
            const unsigned kb = smK + (buf ^ 1) * 18432u;
            const unsigned vb = smV + (buf ^ 1) * 18432u;
            #pragma unroll
            for (int t = 0; t < 2; t++) {
                unsigned so = (unsigned)((ld_row[t]*72 + ld_c8[t]) * 2);
                size_t go = gofs + (size_t)ld_row[t]*64 + ld_c8[t];
                CP16(kb + so,         g_Kh + go);
                CP16(kb + 9216u + so, g_Kl + go);
                CP16(vb + so,         g_Vh + go);
                CP16(vb + 9216u + so, g_Vl + go);
            }
        }
        CP_COMMIT();
        CP_WAIT1();
        __syncthreads();   // (A)

        __nv_bfloat16* sKh = (__nv_bfloat16*)(sm + ATT_K + buf*18432);
        __nv_bfloat16* sKl = (__nv_bfloat16*)(sm + ATT_K + buf*18432 + 9216);
        __nv_bfloat16* sVh = (__nv_bfloat16*)(sm + ATT_V + buf*18432);
        __nv_bfloat16* sVl = (__nv_bfloat16*)(sm + ATT_V + buf*18432 + 9216);

        float s[4][2][4];
        #pragma unroll
        for (int i = 0; i < 4; i++)
            #pragma unroll
            for (int j = 0; j < 2; j++)
                #pragma unroll
                for (int e = 0; e < 4; e++) s[i][j][e] = 0.f;

        #pragma unroll
        for (int kk = 0; kk < 64; kk += 16) {
            unsigned a[4][4], bhf[2][2], blf[2][2], t4[4];
            #pragma unroll
            for (int mi = 0; mi < 4; mi++)
                ldsm4(a[mi], smem_u32(&sQh[(wm*64 + mi*16 + l15)*72 + kk + lh8]));
            ldsm4(t4, smem_u32(&sKh[(wn*16 + bn)*72 + kk + bk8]));
            bhf[0][0]=t4[0]; bhf[0][1]=t4[1]; bhf[1][0]=t4[2]; bhf[1][1]=t4[3];
            ldsm4(t4, smem_u32(&sKl[(wn*16 + bn)*72 + kk + bk8]));
            blf[0][0]=t4[0]; blf[0][1]=t4[1]; blf[1][0]=t4[2]; blf[1][1]=t4[3];
            #pragma unroll
            for (int mi = 0; mi < 4; mi++)
                #pragma unroll
                for (int ni = 0; ni < 2; ni++) mma_bf(s[mi][ni], a[mi], bhf[ni]);
            #pragma unroll
            for (int mi = 0; mi < 4; mi++)
                #pragma unroll
                for (int ni = 0; ni < 2; ni++) mma_bf(s[mi][ni], a[mi], blf[ni]);
            #pragma unroll
            for (int mi = 0; mi < 4; mi++)
                ldsm4(a[mi], smem_u32(&sQl[(wm*64 + mi*16 + l15)*72 + kk + lh8]));
            #pragma unroll
            for (int mi = 0; mi < 4; mi++)
                #pragma unroll
                for (int ni = 0; ni < 2; ni++) mma_bf(s[mi][ni], a[mi], bhf[ni]);
        }

        const int k0g = kt << 6;
        #pragma unroll
        for (int mi = 0; mi < 4; mi++) {
            float sumA = 0.f, sumB = 0.f;
            const int rowA = wm*64 + mi*16 + rA0;
            #pragma unroll
            for (int ni = 0; ni < 2; ni++) {
                const int col = wn*16 + ni*8 + c2;
                const bool v0 = (k0g + col)     < nv;
                const bool v1 = (k0g + col + 1) < nv;
                float p00 = v0 ? __expf(s[mi][ni][0]*SCALE_) : 0.f;
                float p01 = v1 ? __expf(s[mi][ni][1]*SCALE_) : 0.f;
                float p10 = v0 ? __expf(s[mi][ni][2]*SCALE_) : 0.f;
                float p11 = v1 ? __expf(s[mi][ni][3]*SCALE_) : 0.f;
                sumA += p00 + p01;  sumB += p10 + p11;
                __nv_bfloat16 h00 = __float2bfloat16_rn(p00);
                __nv_bfloat16 h01 = __float2bfloat16_rn(p01);
                __nv_bfloat16 h10 = __float2bfloat16_rn(p10);
                __nv_bfloat16 h11 = __float2bfloat16_rn(p11);
                __nv_bfloat162 vh0; vh0.x=h00; vh0.y=h01;
                __nv_bfloat162 vh1; vh1.x=h10; vh1.y=h11;
                __nv_bfloat162 vl0, vl1;
                vl0.x = __float2bfloat16_rn(p00 - __bfloat162float(h00));
                vl0.y = __float2bfloat16_rn(p01 - __bfloat162float(h01));
                vl1.x = __float2bfloat16_rn(p10 - __bfloat162float(h10));
                vl1.y = __float2bfloat16_rn(p11 - __bfloat162float(h11));
                *(__nv_bfloat162*)(sPh + rowA*72 + col)      = vh0;
                *(__nv_bfloat162*)(sPh + (rowA+8)*72 + col)  = vh1;
                *(__nv_bfloat162*)(sPl + rowA*72 + col)      = vl0;
                *(__nv_bfloat162*)(sPl + (rowA+8)*72 + col)  = vl1;
            }
            sumA += __shfl_xor_sync(0xffffffffu, sumA, 1);
            sumA += __shfl_xor_sync(0xffffffffu, sumA, 2);
            sumB += __shfl_xor_sync(0xffffffffu, sumB, 1);
            sumB += __shfl_xor_sync(0xffffffffu, sumB, 2);
            if ((lane & 3) == 0) {
                psum[rowA*4 + wn]     = sumA;
                psum[(rowA+8)*4 + wn] = sumB;
            }
        }
        __syncthreads();   // (B)

        if (tid < 128)
            l_s[tid] += psum[tid*4+0] + psum[tid*4+1] + psum[tid*4+2] + psum[tid*4+3];

        #pragma unroll
        for (int kk = 0; kk < 64; kk += 16) {
            unsigned pa[4][4], vhf[2][2], vlf[2][2], t4[4];
            #pragma unroll
            for (int mi = 0; mi < 4; mi++)
                ldsm4(pa[mi], smem_u32(&sPh[(wm*64 + mi*16 + l15)*72 + kk + lh8]));
            ldsm4t(t4, smem_u32(&sVh[(kk + l15)*72 + wn*16 + lh8]));
            vhf[0][0]=t4[0]; vhf[0][1]=t4[1]; vhf[1][0]=t4[2]; vhf[1][1]=t4[3];
            ldsm4t(t4, smem_u32(&sVl[(kk + l15)*72 + wn*16 + lh8]));
            vlf[0][0]=t4[0]; vlf[0][1]=t4[1]; vlf[1][0]=t4[2]; vlf[1][1]=t4[3];
            #pragma unroll
            for (int mi = 0; mi < 4; mi++)
                #pragma unroll
                for (int ni = 0; ni < 2; ni++) mma_bf(o[mi][ni], pa[mi], vhf[ni]);
            #pragma unroll
            for (int mi = 0; mi < 4; mi++)
                #pragma unroll
                for (int ni = 0; ni < 2; ni++) mma_bf(o[mi][ni], pa[mi], vlf[ni]);
            #pragma unroll
            for (int mi = 0; mi < 4; mi++)
                ldsm4(pa[mi], smem_u32(&sPl[(wm*64 + mi*16 + l15)*72 + kk + lh8]));
            #pragma unroll
            for (int mi = 0; mi < 4; mi++)
                #pragma unroll
                for (int ni = 0; ni < 2; ni++) mma_bf(o[mi][ni], pa[mi], vhf[ni]);
        }
        __syncthreads();   // (C)
    }

    #pragma unroll
    for (int mi = 0; mi < 4; mi++) {
        const int rowA = wm*64 + mi*16 + rA0, rowB = rowA + 8;
        const float invA = 1.f / l_s[rowA], invB = 1.f / l_s[rowB];
        #pragma unroll
        for (int ni = 0; ni < 2; ni++) {
            const int col = wn*16 + ni*8 + c2;
            float2 w0; w0.x = o[mi][ni][0]*invA; w0.y = o[mi][ni][1]*invA;
            float2 w1; w1.x = o[mi][ni][2]*invB; w1.y = o[mi][ni][3]*invB;
            *(float2*)(g_CTX + (size_t)(bb*T_ + qt0 + rowA)*D_ + hh*64 + col) = w0;
            *(float2*)(g_CTX + (size_t)(bb*T_ + qt0 + rowB)*D_ + hh*64 + col) = w1;
        }
    }
}

// ============================================================================
extern "C" void kernel_launch(void* const* d_in, const int* in_sizes, int n_in,
                              void* d_out, int out_size)
{
    const float* q  = (const float*)d_in[0];
    const float* k  = (const float*)d_in[1];
    const float* v  = (const float*)d_in[2];
    const int*  mk  = (const int*)  d_in[3];
    const float* Wq = (const float*)d_in[4];
    const float* bq = (const float*)d_in[5];
    const float* Wk = (const float*)d_in[6];
    const float* bk = (const float*)d_in[7];
    const float* Wv = (const float*)d_in[8];
    const float* bv = (const float*)d_in[9];
    const float* Wo = (const float*)d_in[10];
    const float* bo = (const float*)d_in[11];
    float* out = (float*)d_out;

    float* pCTX;
    __nv_bfloat16 *pAh, *pAl, *pWh, *pWl, *pQh, *pQl, *pKh, *pKl, *pVh, *pVl;
    cudaGetSymbolAddress((void**)&pCTX, g_CTX);
    cudaGetSymbolAddress((void**)&pAh, g_Ah);
    cudaGetSymbolAddress((void**)&pAl, g_Al);
    cudaGetSymbolAddress((void**)&pWh, g_Wh);
    cudaGetSymbolAddress((void**)&pWl, g_Wl);
    cudaGetSymbolAddress((void**)&pQh, g_Qh);
    cudaGetSymbolAddress((void**)&pQl, g_Ql);
    cudaGetSymbolAddress((void**)&pKh, g_Kh);
    cudaGetSymbolAddress((void**)&pKl, g_Kl);
    cudaGetSymbolAddress((void**)&pVh, g_Vh);
    cudaGetSymbolAddress((void**)&pVl, g_Vl);

    cudaFuncSetAttribute(gemm_mma,
                         cudaFuncAttributeMaxDynamicSharedMemorySize, GEMM_SMEM);
    cudaFuncSetAttribute(attn_mma,
                         cudaFuncAttributeMaxDynamicSharedMemorySize, ATT_SMEM);

    dim3 blk(256);
    dim3 gG(8, 32);

    scan_mask<<<B_, 1024>>>(mk);

    // Q projection (hi+lo, [B,H,T,64] scatter)
    conv_split<<<4096, blk>>>(q, pAh, pAl, 1048576);
    conv_split<<<1024, blk>>>(Wq, pWh, pWl, 262144);
    gemm_mma<<<gG, blk, GEMM_SMEM>>>(pAh, pAl, pWh, pWl, bq, nullptr, pQh, pQl, 0);
    // K projection (compacted hi+lo)
    conv_split<<<4096, blk>>>(k, pAh, pAl, 1048576);
    conv_split<<<1024, blk>>>(Wk, pWh, pWl, 262144);
    gemm_mma<<<gG, blk, GEMM_SMEM>>>(pAh, pAl, pWh, pWl, bk, nullptr, pKh, pKl, 1);
    // V projection (compacted hi+lo)
    conv_split<<<4096, blk>>>(v, pAh, pAl, 1048576);
    conv_split<<<1024, blk>>>(Wv, pWh, pWl, 262144);
    gemm_mma<<<gG, blk, GEMM_SMEM>>>(pAh, pAl, pWh, pWl, bv, nullptr, pVh, pVl, 1);
    // Attention over compacted keys
    attn_mma<<<dim3(16, 16, 2), blk, ATT_SMEM>>>();
    // Output projection
    conv_split<<<4096, blk>>>(pCTX, pAh, pAl, 1048576);
    conv_split<<<1024, blk>>>(Wo, pWh, pWl, 262144);
    gemm_mma<<<gG, blk, GEMM_SMEM>>>(pAh, pAl, pWh, pWl, bo, out, nullptr, nullptr, 2);
}

// round 8
// speedup vs baseline: 1.1162x; 1.1162x over previous
#include <cuda_runtime.h>
#include <cuda_bf16.h>
#include <math.h>
#include <stdint.h>

#define B_ 2
#define T_ 2048
#define D_ 1024
#define H_ 16
#define DH_ 64
#define SCALE_ 0.03125f     /* 1/sqrt(1024) exactly */

#define ASTRIDE ((size_t)4096*1024)
#define WSTRIDE ((size_t)1024*1024)

// ============================================================================
// Scratch (static device globals — no allocation in kernel_launch)
// ============================================================================
__device__ float g_CTX[(size_t)B_*T_*D_];
__device__ __nv_bfloat16 g_Ah[3*ASTRIDE];
__device__ __nv_bfloat16 g_Al[3*ASTRIDE];
__device__ __nv_bfloat16 g_Wh[4*WSTRIDE];
__device__ __nv_bfloat16 g_Wl[4*WSTRIDE];
__device__ __nv_bfloat16 g_Qh[(size_t)B_*H_*T_*DH_];
__device__ __nv_bfloat16 g_Ql[(size_t)B_*H_*T_*DH_];
__device__ __nv_bfloat16 g_Kh[(size_t)B_*H_*T_*DH_];   // compacted
__device__ __nv_bfloat16 g_Kl[(size_t)B_*H_*T_*DH_];   // compacted
__device__ __nv_bfloat16 g_Vh[(size_t)B_*H_*T_*DH_];   // compacted
__device__ __nv_bfloat16 g_Vl[(size_t)B_*H_*T_*DH_];   // compacted
__device__ int g_pos[B_*T_];
__device__ int g_cnt[B_];

// ============================================================================
// mma.sync / ldmatrix / cp.async helpers (base-target PTX)
// ============================================================================
__device__ __forceinline__ unsigned smem_u32(const void* p) {
    unsigned a;
    asm("{ .reg .u64 t; cvta.to.shared.u64 t, %1; cvt.u32.u64 %0, t; }"
        : "=r"(a) : "l"(p));
    return a;
}
__device__ __forceinline__ void mma_bf(float* c, const unsigned* a, const unsigned* b) {
    asm volatile(
        "mma.sync.aligned.m16n8k16.row.col.f32.bf16.bf16.f32 "
        "{%0,%1,%2,%3}, {%4,%5,%6,%7}, {%8,%9}, {%0,%1,%2,%3};"
        : "+f"(c[0]), "+f"(c[1]), "+f"(c[2]), "+f"(c[3])
        : "r"(a[0]), "r"(a[1]), "r"(a[2]), "r"(a[3]), "r"(b[0]), "r"(b[1]));
}
__device__ __forceinline__ void ldsm4(unsigned* r, unsigned a) {
    asm volatile("ldmatrix.sync.aligned.m8n8.x4.shared.b16 {%0,%1,%2,%3}, [%4];"
        : "=r"(r[0]), "=r"(r[1]), "=r"(r[2]), "=r"(r[3]) : "r"(a));
}
__device__ __forceinline__ void ldsm4t(unsigned* r, unsigned a) {
    asm volatile("ldmatrix.sync.aligned.m8n8.x4.trans.shared.b16 {%0,%1,%2,%3}, [%4];"
        : "=r"(r[0]), "=r"(r[1]), "=r"(r[2]), "=r"(r[3]) : "r"(a));
}
#define CP16(dst_u32, src_ptr) \
    asm volatile("cp.async.cg.shared.global [%0], [%1], 16;" \
        :: "r"(dst_u32), "l"(src_ptr) : "memory")
#define CP_COMMIT() asm volatile("cp.async.commit_group;" ::: "memory")
#define CP_WAIT1()  asm volatile("cp.async.wait_group 1;"  ::: "memory")

// ============================================================================
// scan_mask
// ============================================================================
__global__ void __launch_bounds__(1024) scan_mask(const int* __restrict__ mask)
{
    __shared__ int ps[1024];
    const int b = blockIdx.x, i = threadIdx.x;
    const int a0 = (mask[b*T_ + 2*i]     != 0);
    const int a1 = (mask[b*T_ + 2*i + 1] != 0);
    ps[i] = a0 + a1;
    __syncthreads();
    for (int off = 1; off < 1024; off <<= 1) {
        int v = ps[i] + ((i >= off) ? ps[i - off] : 0);
        __syncthreads();
        ps[i] = v;
        __syncthreads();
    }
    const int excl = (i > 0) ? ps[i-1] : 0;
    g_pos[b*T_ + 2*i]     = a0 ? excl : -1;
    g_pos[b*T_ + 2*i + 1] = a1 ? (excl + a0) : -1;
    if (i == 1023) g_cnt[b] = ps[1023];
}

// ============================================================================
// conv_split core + batched wrappers
// ============================================================================
__device__ __forceinline__ void conv_one(
    const float* __restrict__ x, __nv_bfloat16* __restrict__ hi,
    __nv_bfloat16* __restrict__ lo, int i)
{
    float4 v = ((const float4*)x)[i];
    __nv_bfloat16 h0 = __float2bfloat16_rn(v.x);
    __nv_bfloat16 h1 = __float2bfloat16_rn(v.y);
    __nv_bfloat16 h2 = __float2bfloat16_rn(v.z);
    __nv_bfloat16 h3 = __float2bfloat16_rn(v.w);
    __nv_bfloat162 ha; ha.x = h0; ha.y = h1;
    __nv_bfloat162 hb; hb.x = h2; hb.y = h3;
    __nv_bfloat162 la, lb;
    la.x = __float2bfloat16_rn(v.x - __bfloat162float(h0));
    la.y = __float2bfloat16_rn(v.y - __bfloat162float(h1));
    lb.x = __float2bfloat16_rn(v.z - __bfloat162float(h2));
    lb.y = __float2bfloat16_rn(v.w - __bfloat162float(h3));
    ((__nv_bfloat162*)hi)[2*i]   = ha;
    ((__nv_bfloat162*)hi)[2*i+1] = hb;
    ((__nv_bfloat162*)lo)[2*i]   = la;
    ((__nv_bfloat162*)lo)[2*i+1] = lb;
}

// z in {0,1,2}: q,k,v -> g_Ah/g_Al slab z
__global__ void __launch_bounds__(256) convA3(
    const float* __restrict__ q, const float* __restrict__ k,
    const float* __restrict__ v,
    __nv_bfloat16* __restrict__ hiB, __nv_bfloat16* __restrict__ loB)
{
    const int z = blockIdx.y;
    const float* src = (z == 0) ? q : (z == 1) ? k : v;
    int i = blockIdx.x * 256 + threadIdx.x;
    conv_one(src, hiB + z*ASTRIDE, loB + z*ASTRIDE, i);
}

// single tensor (ctx) -> slab 0
__global__ void __launch_bounds__(256) convA1(
    const float* __restrict__ x,
    __nv_bfloat16* __restrict__ hiB, __nv_bfloat16* __restrict__ loB)
{
    int i = blockIdx.x * 256 + threadIdx.x;
    conv_one(x, hiB, loB, i);
}

// z in {0..3}: Wq,Wk,Wv,Wo -> g_Wh/g_Wl slab z
__global__ void __launch_bounds__(256) convW4(
    const float* __restrict__ wq, const float* __restrict__ wk,
    const float* __restrict__ wv, const float* __restrict__ wo,
    __nv_bfloat16* __restrict__ hiB, __nv_bfloat16* __restrict__ loB)
{
    const int z = blockIdx.y;
    const float* src = (z == 0) ? wq : (z == 1) ? wk : (z == 2) ? wv : wo;
    int i = blockIdx.x * 256 + threadIdx.x;
    conv_one(src, hiB + z*WSTRIDE, loB + z*WSTRIDE, i);
}

// ============================================================================
// GEMM core (split-bf16 3-stream, cp.async 2-stage pipeline)
// ============================================================================
#define GST 37888
#define G_AL_OFF 10240
#define G_WH_OFF 20480
#define G_WL_OFF 29184
#define GEMM_SMEM (2*GST)

__device__ __forceinline__ void gemm_core(
    char* gsm,
    const __nv_bfloat16* __restrict__ Ah, const __nv_bfloat16* __restrict__ Al,
    const __nv_bfloat16* __restrict__ Wh, const __nv_bfloat16* __restrict__ Wl,
    const float* __restrict__ bias,
    float* __restrict__ Yf,
    __nv_bfloat16* __restrict__ Yh, __nv_bfloat16* __restrict__ Yl,
    int mode, int m0, int n0)
{
    const int tid = threadIdx.x, lane = tid & 31, wid = tid >> 5;
    const int wm = wid >> 2, wn = wid & 3;

    float c[4][4][4];
    #pragma unroll
    for (int i = 0; i < 4; i++)
        #pragma unroll
        for (int j = 0; j < 4; j++)
            #pragma unroll
            for (int e = 0; e < 4; e++) c[i][j][e] = 0.f;

    const int l15 = lane & 15, lh8 = (lane >> 4) << 3;
    const unsigned smb = smem_u32(gsm);

    int a_row[2], a_c8[2], w_row[2], w_c8[2];
    #pragma unroll
    for (int t = 0; t < 2; t++) {
        int ch = tid + t*256;
        a_row[t] = ch >> 2;  a_c8[t] = (ch & 3) << 3;
        w_row[t] = ch >> 4;  w_c8[t] = (ch & 15) << 3;
    }

    auto issue = [&](int s, int k0) {
        const unsigned base = smb + s*GST;
        #pragma unroll
        for (int t = 0; t < 2; t++) {
            unsigned aso = base + (unsigned)(a_row[t]*80 + a_c8[t]*2);
            size_t ago = (size_t)(m0 + a_row[t])*1024 + k0 + a_c8[t];
            CP16(aso,            Ah + ago);
            CP16(aso + G_AL_OFF, Al + ago);
            unsigned wso = base + G_WH_OFF + (unsigned)(w_row[t]*272 + w_c8[t]*2);
            size_t wgo = (size_t)(k0 + w_row[t])*1024 + n0 + w_c8[t];
            CP16(wso,                       Wh + wgo);
            CP16(wso + (G_WL_OFF-G_WH_OFF), Wl + wgo);
        }
    };

    issue(0, 0);
    CP_COMMIT();

    for (int kc = 0; kc < 32; kc++) {
        const int buf = kc & 1;
        if (kc + 1 < 32) issue(buf ^ 1, (kc+1) << 5);
        CP_COMMIT();
        CP_WAIT1();
        __syncthreads();

        const __nv_bfloat16* sAh = (const __nv_bfloat16*)(gsm + buf*GST);
        const __nv_bfloat16* sAl = (const __nv_bfloat16*)(gsm + buf*GST + G_AL_OFF);
        const __nv_bfloat16* sWh = (const __nv_bfloat16*)(gsm + buf*GST + G_WH_OFF);
        const __nv_bfloat16* sWl = (const __nv_bfloat16*)(gsm + buf*GST + G_WL_OFF);

        #pragma unroll
        for (int kk = 0; kk < 32; kk += 16) {
            unsigned a[4][4], bh_[4][2], bl_[4][2], t4[4];
            #pragma unroll
            for (int mi = 0; mi < 4; mi++)
                ldsm4(a[mi], smem_u32(&sAh[(wm*64 + mi*16 + l15)*40 + kk + lh8]));
            #pragma unroll
            for (int p = 0; p < 2; p++) {
                ldsm4t(t4, smem_u32(&sWh[(kk + l15)*136 + wn*32 + p*16 + lh8]));
                bh_[2*p][0]=t4[0]; bh_[2*p][1]=t4[1];
                bh_[2*p+1][0]=t4[2]; bh_[2*p+1][1]=t4[3];
                ldsm4t(t4, smem_u32(&sWl[(kk + l15)*136 + wn*32 + p*16 + lh8]));
                bl_[2*p][0]=t4[0]; bl_[2*p][1]=t4[1];
                bl_[2*p+1][0]=t4[2]; bl_[2*p+1][1]=t4[3];
            }
            #pragma unroll
            for (int mi = 0; mi < 4; mi++)
                #pragma unroll
                for (int ni = 0; ni < 4; ni++) mma_bf(c[mi][ni], a[mi], bh_[ni]);
            #pragma unroll
            for (int mi = 0; mi < 4; mi++)
                #pragma unroll
                for (int ni = 0; ni < 4; ni++) mma_bf(c[mi][ni], a[mi], bl_[ni]);
            #pragma unroll
            for (int mi = 0; mi < 4; mi++)
                ldsm4(a[mi], smem_u32(&sAl[(wm*64 + mi*16 + l15)*40 + kk + lh8]));
            #pragma unroll
            for (int mi = 0; mi < 4; mi++)
                #pragma unroll
                for (int ni = 0; ni < 4; ni++) mma_bf(c[mi][ni], a[mi], bh_[ni]);
        }
        __syncthreads();
    }

    // Epilogue
    const int rA = lane >> 2, c2 = (lane & 3) << 1;
    #pragma unroll
    for (int mi = 0; mi < 4; mi++) {
        const int rowA = m0 + wm*64 + mi*16 + rA;
        const int rowB = rowA + 8;
        int pA = rowA & (T_-1), pB = rowB & (T_-1);
        if (mode == 1) { pA = g_pos[rowA]; pB = g_pos[rowB]; }
        #pragma unroll
        for (int ni = 0; ni < 4; ni++) {
            const int col = n0 + wn*32 + ni*8 + c2;
            float2 bb = *(const float2*)(bias + col);
            float v00 = c[mi][ni][0] + bb.x, v01 = c[mi][ni][1] + bb.y;
            float v10 = c[mi][ni][2] + bb.x, v11 = c[mi][ni][3] + bb.y;
            if (mode == 2) {
                float2 w0; w0.x = v00; w0.y = v01;
                float2 w1; w1.x = v10; w1.y = v11;
                *(float2*)(Yf + (size_t)rowA * 1024 + col) = w0;
                *(float2*)(Yf + (size_t)rowB * 1024 + col) = w1;
            } else {
                const int hh = col >> 6, dd = col & 63;
                const int bA = rowA >> 11, bB = rowB >> 11;
                __nv_bfloat16 h00 = __float2bfloat16_rn(v00);
                __nv_bfloat16 h01 = __float2bfloat16_rn(v01);
                __nv_bfloat16 h10 = __float2bfloat16_rn(v10);
                __nv_bfloat16 h11 = __float2bfloat16_rn(v11);
                __nv_bfloat162 ph0; ph0.x=h00; ph0.y=h01;
                __nv_bfloat162 ph1; ph1.x=h10; ph1.y=h11;
                __nv_bfloat162 pl0, pl1;
                pl0.x = __float2bfloat16_rn(v00 - __bfloat162float(h00));
                pl0.y = __float2bfloat16_rn(v01 - __bfloat162float(h01));
                pl1.x = __float2bfloat16_rn(v10 - __bfloat162float(h10));
                pl1.y = __float2bfloat16_rn(v11 - __bfloat162float(h11));
                if (pA >= 0) {
                    size_t oA = (((size_t)(bA*H_ + hh))*T_ + pA)*64 + dd;
                    *(__nv_bfloat162*)(Yh + oA) = ph0;
                    *(__nv_bfloat162*)(Yl + oA) = pl0;
                }
                if (pB >= 0) {
                    size_t oB = (((size_t)(bB*H_ + hh))*T_ + pB)*64 + dd;
                    *(__nv_bfloat162*)(Yh + oB) = ph1;
                    *(__nv_bfloat162*)(Yl + oB) = pl1;
                }
            }
        }
    }
}

// Batched QKV projection: blockIdx.z selects {Q,K,V}
__global__ void __launch_bounds__(256, 2) gemm_qkv(
    const __nv_bfloat16* __restrict__ AhB, const __nv_bfloat16* __restrict__ AlB,
    const __nv_bfloat16* __restrict__ WhB, const __nv_bfloat16* __restrict__ WlB,
    const float* __restrict__ bq, const float* __restrict__ bk,
    const float* __restrict__ bv,
    __nv_bfloat16* __restrict__ Qh, __nv_bfloat16* __restrict__ Ql,
    __nv_bfloat16* __restrict__ Kh, __nv_bfloat16* __restrict__ Kl,
    __nv_bfloat16* __restrict__ Vh, __nv_bfloat16* __restrict__ Vl)
{
    extern __shared__ __align__(16) char gsm[];
    const int z = blockIdx.z;
    const float* bias = (z == 0) ? bq : (z == 1) ? bk : bv;
    __nv_bfloat16* Yh = (z == 0) ? Qh : (z == 1) ? Kh : Vh;
    __nv_bfloat16* Yl = (z == 0) ? Ql : (z == 1) ? Kl : Vl;
    gemm_core(gsm, AhB + z*ASTRIDE, AlB + z*ASTRIDE,
              WhB + z*WSTRIDE, WlB + z*WSTRIDE, bias,
              nullptr, Yh, Yl, (z == 0) ? 0 : 1,
              blockIdx.y << 7, blockIdx.x << 7);
}

// Output projection (dense fp32)
__global__ void __launch_bounds__(256, 2) gemm_out(
    const __nv_bfloat16* __restrict__ AhB, const __nv_bfloat16* __restrict__ AlB,
    const __nv_bfloat16* __restrict__ WhB, const __nv_bfloat16* __restrict__ WlB,
    const float* __restrict__ bo, float* __restrict__ out)
{
    extern __shared__ __align__(16) char gsm[];
    gemm_core(gsm, AhB, AlB, WhB + 3*WSTRIDE, WlB + 3*WSTRIDE, bo,
              out, nullptr, nullptr, 2, blockIdx.y << 7, blockIdx.x << 7);
}

// ============================================================================
// Flash attention (unchanged from R5/R6 passing version)
// ============================================================================
#define ATT_QH   0
#define ATT_QL   18432
#define ATT_K    36864
#define ATT_V    73728
#define ATT_PH   110592
#define ATT_PL   129024
#define ATT_PSUM 147456
#define ATT_LS   149504
#define ATT_SMEM 150016

__global__ void __launch_bounds__(256) attn_mma()
{
    extern __shared__ __align__(16) char sm[];
    __nv_bfloat16* sQh = (__nv_bfloat16*)(sm + ATT_QH);
    __nv_bfloat16* sQl = (__nv_bfloat16*)(sm + ATT_QL);
    __nv_bfloat16* sPh = (__nv_bfloat16*)(sm + ATT_PH);
    __nv_bfloat16* sPl = (__nv_bfloat16*)(sm + ATT_PL);
    float* psum = (float*)(sm + ATT_PSUM);
    float* l_s  = (float*)(sm + ATT_LS);

    const int tid = threadIdx.x, lane = tid & 31, wid = tid >> 5;
    const int wm = wid >> 2, wn = wid & 3;
    const int qt0 = blockIdx.x << 7;
    const int hh = blockIdx.y, bb = blockIdx.z;
    const size_t base = ((size_t)(bb*H_ + hh)) * T_ * DH_;
    const int nv = g_cnt[bb];
    const int nt = (nv + 63) >> 6;

    const int r = tid >> 1, cofs = (tid & 1) << 5;
    const int l15 = lane & 15, lh8 = (lane >> 4) << 3;
    const int bn  = (lane & 7) + ((lane >> 4) << 3), bk8 = ((lane >> 3) & 1) << 3;
    const int rA0 = lane >> 2, c2 = (lane & 3) << 1;

    const unsigned smK = smem_u32(sm + ATT_K);
    const unsigned smV = smem_u32(sm + ATT_V);

    int ld_row[2], ld_c8[2];
    #pragma unroll
    for (int t = 0; t < 2; t++) {
        int ch = tid + t*256;
        ld_row[t] = ch >> 3;
        ld_c8[t]  = (ch & 7) << 3;
    }

    {
        const uint4* s1 = (const uint4*)(g_Qh + base + (size_t)(qt0 + r)*64 + cofs);
        uint4* d1 = (uint4*)(sQh + r*72 + cofs);
        d1[0]=s1[0]; d1[1]=s1[1]; d1[2]=s1[2]; d1[3]=s1[3];
        const uint4* s2 = (const uint4*)(g_Ql + base + (size_t)(qt0 + r)*64 + cofs);
        uint4* d2 = (uint4*)(sQl + r*72 + cofs);
        d2[0]=s2[0]; d2[1]=s2[1]; d2[2]=s2[2]; d2[3]=s2[3];
    }
    if (tid < 128) l_s[tid] = 0.f;

    float o[4][2][4];
    #pragma unroll
    for (int i = 0; i < 4; i++)
        #pragma unroll
        for (int j = 0; j < 2; j++)
            #pragma unroll
            for (int e = 0; e < 4; e++) o[i][j][e] = 0.f;

    #pragma unroll
    for (int t = 0; t < 2; t++) {
        unsigned so = (unsigned)((ld_row[t]*72 + ld_c8[t]) * 2);
        size_t go = base + (size_t)ld_row[t]*64 + ld_c8[t];
        CP16(smK + so,         g_Kh + go);
        CP16(smK + 9216u + so, g_Kl + go);
        CP16(smV + so,         g_Vh + go);
        CP16(smV + 9216u + so, g_Vl + go);
    }
    CP_COMMIT();

    for (int kt = 0; kt < nt; kt++) {
        const int buf = kt & 1;
        if (kt + 1 < nt) {
            const size_t gofs = base + ((size_t)(kt+1) << 6) * 64;
            const unsigned kb = smK + (buf ^ 1) * 18432u;
            const unsigned vb = smV + (buf ^ 1) * 18432u;
            #pragma unroll
            for (int t = 0; t < 2; t++) {
                unsigned so = (unsigned)((ld_row[t]*72 + ld_c8[t]) * 2);
                size_t go = gofs + (size_t)ld_row[t]*64 + ld_c8[t];
                CP16(kb + so,         g_Kh + go);
                CP16(kb + 9216u + so, g_Kl + go);
                CP16(vb + so,         g_Vh + go);
                CP16(vb + 9216u + so, g_Vl + go);
            }
        }
        CP_COMMIT();
        CP_WAIT1();
        __syncthreads();   // (A)

        __nv_bfloat16* sKh = (__nv_bfloat16*)(sm + ATT_K + buf*18432);
        __nv_bfloat16* sKl = (__nv_bfloat16*)(sm + ATT_K + buf*18432 + 9216);
        __nv_bfloat16* sVh = (__nv_bfloat16*)(sm + ATT_V + buf*18432);
        __nv_bfloat16* sVl = (__nv_bfloat16*)(sm + ATT_V + buf*18432 + 9216);

        float s[4][2][4];
        #pragma unroll
        for (int i = 0; i < 4; i++)
            #pragma unroll
            for (int j = 0; j < 2; j++)
                #pragma unroll
                for (int e = 0; e < 4; e++) s[i][j][e] = 0.f;

        #pragma unroll
        for (int kk = 0; kk < 64; kk += 16) {
            unsigned a[4][4], bhf[2][2], blf[2][2], t4[4];
            #pragma unroll
            for (int mi = 0; mi < 4; mi++)
                ldsm4(a[mi], smem_u32(&sQh[(wm*64 + mi*16 + l15)*72 + kk + lh8]));
            ldsm4(t4, smem_u32(&sKh[(wn*16 + bn)*72 + kk + bk8]));
            bhf[0][0]=t4[0]; bhf[0][1]=t4[1]; bhf[1][0]=t4[2]; bhf[1][1]=t4[3];
            ldsm4(t4, smem_u32(&sKl[(wn*16 + bn)*72 + kk + bk8]));
            blf[0][0]=t4[0]; blf[0][1]=t4[1]; blf[1][0]=t4[2]; blf[1][1]=t4[3];
            #pragma unroll
            for (int mi = 0; mi < 4; mi++)
                #pragma unroll
                for (int ni = 0; ni < 2; ni++) mma_bf(s[mi][ni], a[mi], bhf[ni]);
            #pragma unroll
            for (int mi = 0; mi < 4; mi++)
                #pragma unroll
                for (int ni = 0; ni < 2; ni++) mma_bf(s[mi][ni], a[mi], blf[ni]);
            #pragma unroll
            for (int mi = 0; mi < 4; mi++)
                ldsm4(a[mi], smem_u32(&sQl[(wm*64 + mi*16 + l15)*72 + kk + lh8]));
            #pragma unroll
            for (int mi = 0; mi < 4; mi++)
                #pragma unroll
                for (int ni = 0; ni < 2; ni++) mma_bf(s[mi][ni], a[mi], bhf[ni]);
        }

        const int k0g = kt << 6;
        #pragma unroll
        for (int mi = 0; mi < 4; mi++) {
            float sumA = 0.f, sumB = 0.f;
            const int rowA = wm*64 + mi*16 + rA0;
            #pragma unroll
            for (int ni = 0; ni < 2; ni++) {
                const int col = wn*16 + ni*8 + c2;
                const bool v0 = (k0g + col)     < nv;
                const bool v1 = (k0g + col + 1) < nv;
                float p00 = v0 ? __expf(s[mi][ni][0]*SCALE_) : 0.f;
                float p01 = v1 ? __expf(s[mi][ni][1]*SCALE_) : 0.f;
                float p10 = v0 ? __expf(s[mi][ni][2]*SCALE_) : 0.f;
                float p11 = v1 ? __expf(s[mi][ni][3]*SCALE_) : 0.f;
                sumA += p00 + p01;  sumB += p10 + p11;
                __nv_bfloat16 h00 = __float2bfloat16_rn(p00);
                __nv_bfloat16 h01 = __float2bfloat16_rn(p01);
                __nv_bfloat16 h10 = __float2bfloat16_rn(p10);
                __nv_bfloat16 h11 = __float2bfloat16_rn(p11);
                __nv_bfloat162 vh0; vh0.x=h00; vh0.y=h01;
                __nv_bfloat162 vh1; vh1.x=h10; vh1.y=h11;
                __nv_bfloat162 vl0, vl1;
                vl0.x = __float2bfloat16_rn(p00 - __bfloat162float(h00));
                vl0.y = __float2bfloat16_rn(p01 - __bfloat162float(h01));
                vl1.x = __float2bfloat16_rn(p10 - __bfloat162float(h10));
                vl1.y = __float2bfloat16_rn(p11 - __bfloat162float(h11));
                *(__nv_bfloat162*)(sPh + rowA*72 + col)      = vh0;
                *(__nv_bfloat162*)(sPh + (rowA+8)*72 + col)  = vh1;
                *(__nv_bfloat162*)(sPl + rowA*72 + col)      = vl0;
                *(__nv_bfloat162*)(sPl + (rowA+8)*72 + col)  = vl1;
            }
            sumA += __shfl_xor_sync(0xffffffffu, sumA, 1);
            sumA += __shfl_xor_sync(0xffffffffu, sumA, 2);
            sumB += __shfl_xor_sync(0xffffffffu, sumB, 1);
            sumB += __shfl_xor_sync(0xffffffffu, sumB, 2);
            if ((lane & 3) == 0) {
                psum[rowA*4 + wn]     = sumA;
                psum[(rowA+8)*4 + wn] = sumB;
            }
        }
        __syncthreads();   // (B)

        if (tid < 128)
            l_s[tid] += psum[tid*4+0] + psum[tid*4+1] + psum[tid*4+2] + psum[tid*4+3];

        #pragma unroll
        for (int kk = 0; kk < 64; kk += 16) {
            unsigned pa[4][4], vhf[2][2], vlf[2][2], t4[4];
            #pragma unroll
            for (int mi = 0; mi < 4; mi++)
                ldsm4(pa[mi], smem_u32(&sPh[(wm*64 + mi*16 + l15)*72 + kk + lh8]));
            ldsm4t(t4, smem_u32(&sVh[(kk + l15)*72 + wn*16 + lh8]));
            vhf[0][0]=t4[0]; vhf[0][1]=t4[1]; vhf[1][0]=t4[2]; vhf[1][1]=t4[3];
            ldsm4t(t4, smem_u32(&sVl[(kk + l15)*72 + wn*16 + lh8]));
            vlf[0][0]=t4[0]; vlf[0][1]=t4[1]; vlf[1][0]=t4[2]; vlf[1][1]=t4[3];
            #pragma unroll
            for (int mi = 0; mi < 4; mi++)
                #pragma unroll
                for (int ni = 0; ni < 2; ni++) mma_bf(o[mi][ni], pa[mi], vhf[ni]);
            #pragma unroll
            for (int mi = 0; mi < 4; mi++)
                #pragma unroll
                for (int ni = 0; ni < 2; ni++) mma_bf(o[mi][ni], pa[mi], vlf[ni]);
            #pragma unroll
            for (int mi = 0; mi < 4; mi++)
                ldsm4(pa[mi], smem_u32(&sPl[(wm*64 + mi*16 + l15)*72 + kk + lh8]));
            #pragma unroll
            for (int mi = 0; mi < 4; mi++)
                #pragma unroll
                for (int ni = 0; ni < 2; ni++) mma_bf(o[mi][ni], pa[mi], vhf[ni]);
        }
        __syncthreads();   // (C)
    }

    #pragma unroll
    for (int mi = 0; mi < 4; mi++) {
        const int rowA = wm*64 + mi*16 + rA0, rowB = rowA + 8;
        const float invA = 1.f / l_s[rowA], invB = 1.f / l_s[rowB];
        #pragma unroll
        for (int ni = 0; ni < 2; ni++) {
            const int col = wn*16 + ni*8 + c2;
            float2 w0; w0.x = o[mi][ni][0]*invA; w0.y = o[mi][ni][1]*invA;
            float2 w1; w1.x = o[mi][ni][2]*invB; w1.y = o[mi][ni][3]*invB;
            *(float2*)(g_CTX + (size_t)(bb*T_ + qt0 + rowA)*D_ + hh*64 + col) = w0;
            *(float2*)(g_CTX + (size_t)(bb*T_ + qt0 + rowB)*D_ + hh*64 + col) = w1;
        }
    }
}

// ============================================================================
extern "C" void kernel_launch(void* const* d_in, const int* in_sizes, int n_in,
                              void* d_out, int out_size)
{
    const float* q  = (const float*)d_in[0];
    const float* k  = (const float*)d_in[1];
    const float* v  = (const float*)d_in[2];
    const int*  mk  = (const int*)  d_in[3];
    const float* Wq = (const float*)d_in[4];
    const float* bq = (const float*)d_in[5];
    const float* Wk = (const float*)d_in[6];
    const float* bk = (const float*)d_in[7];
    const float* Wv = (const float*)d_in[8];
    const float* bv = (const float*)d_in[9];
    const float* Wo = (const float*)d_in[10];
    const float* bo = (const float*)d_in[11];
    float* out = (float*)d_out;

    float* pCTX;
    __nv_bfloat16 *pAh, *pAl, *pWh, *pWl, *pQh, *pQl, *pKh, *pKl, *pVh, *pVl;
    cudaGetSymbolAddress((void**)&pCTX, g_CTX);
    cudaGetSymbolAddress((void**)&pAh, g_Ah);
    cudaGetSymbolAddress((void**)&pAl, g_Al);
    cudaGetSymbolAddress((void**)&pWh, g_Wh);
    cudaGetSymbolAddress((void**)&pWl, g_Wl);
    cudaGetSymbolAddress((void**)&pQh, g_Qh);
    cudaGetSymbolAddress((void**)&pQl, g_Ql);
    cudaGetSymbolAddress((void**)&pKh, g_Kh);
    cudaGetSymbolAddress((void**)&pKl, g_Kl);
    cudaGetSymbolAddress((void**)&pVh, g_Vh);
    cudaGetSymbolAddress((void**)&pVl, g_Vl);

    cudaFuncSetAttribute(gemm_qkv,
                         cudaFuncAttributeMaxDynamicSharedMemorySize, GEMM_SMEM);
    cudaFuncSetAttribute(gemm_out,
                         cudaFuncAttributeMaxDynamicSharedMemorySize, GEMM_SMEM);
    cudaFuncSetAttribute(attn_mma,
                         cudaFuncAttributeMaxDynamicSharedMemorySize, ATT_SMEM);

    dim3 blk(256);

    scan_mask<<<B_, 1024>>>(mk);
    convW4<<<dim3(1024, 4), blk>>>(Wq, Wk, Wv, Wo, pWh, pWl);
    convA3<<<dim3(4096, 3), blk>>>(q, k, v, pAh, pAl);
    gemm_qkv<<<dim3(8, 32, 3), blk, GEMM_SMEM>>>(
        pAh, pAl, pWh, pWl, bq, bk, bv, pQh, pQl, pKh, pKl, pVh, pVl);
    attn_mma<<<dim3(16, 16, 2), blk, ATT_SMEM>>>();
    convA1<<<4096, blk>>>(pCTX, pAh, pAl);
    gemm_out<<<dim3(8, 32), blk, GEMM_SMEM>>>(pAh, pAl, pWh, pWl, bo, out);
}